// round 11
// baseline (speedup 1.0000x reference)
#include <cuda_runtime.h>

#define HID 64
#define NBATCH 256
#define SEQ 4096
#define NG 256   // 4*HID gates

// Scratch (no cudaMalloc allowed).  g_xz has a 4*NG tail pad so the ring
// prefetch can run 4 steps past the end without bounds checks.
__device__ float g_seqA[(size_t)NBATCH * SEQ * HID];          // 256 MB
__device__ float g_seqB[(size_t)NBATCH * SEQ * HID];          // 256 MB
__device__ float g_xz[(size_t)NBATCH * SEQ * NG + 4 * NG];    // 1 GB + pad

typedef unsigned long long ull;

static __device__ __forceinline__ ull pk2(float lo, float hi) {
    ull r;
    asm("mov.b64 %0, {%1,%2};" : "=l"(r) : "f"(lo), "f"(hi));
    return r;
}
static __device__ __forceinline__ void upk2(ull v, float& lo, float& hi) {
    asm("mov.b64 {%0,%1}, %2;" : "=f"(lo), "=f"(hi) : "l"(v));
}
static __device__ __forceinline__ void ffma2(ull& d, ull a, ull b) {
    asm("fma.rn.f32x2 %0, %1, %2, %0;" : "+l"(d) : "l"(a), "l"(b));
}
static __device__ __forceinline__ float ex2f(float x) {
    float r; asm("ex2.approx.f32 %0, %1;" : "=f"(r) : "f"(x)); return r;
}
static __device__ __forceinline__ float rcpf(float x) {
    float r; asm("rcp.approx.f32 %0, %1;" : "=f"(r) : "f"(x)); return r;
}
#define L2E 1.44269504088896f
// tanh(x) = 1 - 2/(2^(2*L2E*x)+1); overflow-safe both directions.
static __device__ __forceinline__ float tanh_f(float x) {
    return fmaf(-2.0f, rcpf(ex2f(x * (2.0f * L2E)) + 1.0f), 1.0f);
}

// gate remap: storage index tid <-> gate row jg = (tid&3)*HID + (tid>>2)

// ---------------------------------------------------------------------------
// xz precompute, DIN = 64 (gate-remapped output), layers 1-2 only.
// ---------------------------------------------------------------------------
__global__ void __launch_bounds__(256)
xz_din64_kernel(const float* __restrict__ in_seq,   // [B,SEQ,64]
                const float* __restrict__ Wih,      // [256,64]
                const float* __restrict__ bih,
                const float* __restrict__ bhh,
                float* __restrict__ xz) {
    __shared__ __align__(16) float sin_[32][HID];   // 8 KB
    const int tid = threadIdx.x;
    const int jg  = (tid & 3) * HID + (tid >> 2);
    const int b   = blockIdx.y;
    const int t0  = blockIdx.x * 32;

    const float* src = in_seq + ((size_t)b * SEQ + t0) * HID;
#pragma unroll
    for (int k = 0; k < 8; ++k)
        ((float*)sin_)[tid + k * 256] = src[tid + k * 256];

    ull wi[32];
#pragma unroll
    for (int p = 0; p < 32; ++p)
        wi[p] = pk2(Wih[jg * HID + 2 * p], Wih[jg * HID + 2 * p + 1]);
    const float bias = bih[jg] + bhh[jg];
    __syncthreads();

    float* o = xz + ((size_t)b * SEQ + t0) * NG + tid;
#pragma unroll 4
    for (int tt = 0; tt < 32; ++tt) {
        const ulonglong2* v = (const ulonglong2*)&sin_[tt][0];
        ull a0 = pk2(bias, 0.0f), a1 = 0ULL;
#pragma unroll
        for (int p = 0; p < 16; ++p) {
            ulonglong2 q = v[p];
            ffma2(a0, wi[2 * p], q.x);
            ffma2(a1, wi[2 * p + 1], q.y);
        }
        float l0, l1, h0, h1;
        upk2(a0, l0, h0); upk2(a1, l1, h1);
        o[(size_t)tt * NG] = (l0 + h0) + (l1 + h1);
    }
}

// ---------------------------------------------------------------------------
// Recurrent kernel.  1 batch/CTA, 256 CTAs x 256 threads, 2 CTAs/SM.
// Thread (u = tid>>2, q = tid&3): partial dots over h-chunk q of all 4 gates
// of unit u.  SEL-FREE REDUCE: accumulator a holds gate (q^a)'s row, so the
// two xor-rounds align gates automatically:
//   kX = p0 + shfl_xor(p2,2); kY = p1 + shfl_xor(p3,2); tot = kX + shfl_xor(kY,1)
// leaves lane q holding gate q fully reduced (bitwise-identical add order).
// Unified activation (1 ex2 + 1 rcp).  Role-mapped 3-shuffle gather: lanes
// read (f,g,o) at xor 1/2/3; mapping is correct on q==0 only, and only q==0's
// c/h are consumed.  1 barrier/step.  h double-buffered in padded smem.
// ---------------------------------------------------------------------------
template <bool DIN1>
__global__ void __launch_bounds__(256, 2)
lstm_rec_kernel(const float* __restrict__ x,        // DIN1: [B,SEQ]
                const float* __restrict__ xz,       // !DIN1: [B,SEQ,256] remapped
                const float* __restrict__ Wih,      // DIN1: [256,1]
                const float* __restrict__ bih,
                const float* __restrict__ bhh,
                const float* __restrict__ Whh,      // [256,64]
                float* __restrict__ out_seq,        // [B,SEQ,64]
                float* __restrict__ d_out,
                int layer) {
    __shared__ __align__(16) float sh[2][80];       // 4 chunks * stride 20

    const int tid = threadIdx.x;
    const int b   = blockIdx.x;
    const int u   = tid >> 2;
    const int q   = tid & 3;
    const int jg  = q * HID + u;

    // weights: accumulator a holds gate (q^a)'s row of unit u over cols
    // [16q, 16q+16)  -> xor-reduce needs no selects
    ull w[32];
#pragma unroll
    for (int a = 0; a < 4; ++a) {
        const int row = (q ^ a) * HID + u;
#pragma unroll
        for (int m = 0; m < 8; ++m)
            w[a * 8 + m] = pk2(Whh[row * HID + 16 * q + 2 * m],
                               Whh[row * HID + 16 * q + 2 * m + 1]);
    }

    // input-contribution state
    float wx = 0.0f, bias = 0.0f;
    const float* xp = nullptr;       // DIN1 input stream
    const float* zpref = nullptr;    // !DIN1 prefetch pointer (t+4 row)
    float ring[4];
    if (DIN1) {
        wx   = Wih[jg];
        bias = bih[jg] + bhh[jg];
        xp = x + (size_t)b * SEQ;
#pragma unroll
        for (int d = 0; d < 4; ++d) ring[d] = xp[d];
    } else {
        const float* z = xz + (size_t)b * SEQ * NG + tid;
#pragma unroll
        for (int d = 0; d < 4; ++d) ring[d] = z[(size_t)d * NG];
        zpref = z + (size_t)4 * NG;
    }

    // activation constants: lane's own gate is tanh iff q==2
    const float sA = (q == 2) ? 2.0f : 1.0f;
    const float kA = sA * L2E;

    float c = 0.0f, hlast = 0.0f;
    if (tid < 160) sh[tid / 80][tid % 80] = 0.0f;
    __syncthreads();

#pragma unroll 4
    for (int t = 0; t < SEQ; ++t) {
        const int par  = t & 1;                     // static under unroll
        const int slot = t & 3;

        // ---- partial dots: 4 gates (xor-permuted) over h-chunk q ----
        const ulonglong2* v = (const ulonglong2*)&sh[par][20 * q];
        ull ac0 = 0ULL, ac1 = 0ULL, ac2 = 0ULL, ac3 = 0ULL;
#pragma unroll
        for (int p = 0; p < 4; ++p) {
            ulonglong2 d = v[p];
            ffma2(ac0, w[0 * 8 + 2 * p], d.x); ffma2(ac0, w[0 * 8 + 2 * p + 1], d.y);
            ffma2(ac1, w[1 * 8 + 2 * p], d.x); ffma2(ac1, w[1 * 8 + 2 * p + 1], d.y);
            ffma2(ac2, w[2 * 8 + 2 * p], d.x); ffma2(ac2, w[2 * 8 + 2 * p + 1], d.y);
            ffma2(ac3, w[3 * 8 + 2 * p], d.x); ffma2(ac3, w[3 * 8 + 2 * p + 1], d.y);
        }
        float p0, p1, p2, p3, lo, hi;
        upk2(ac0, lo, hi); p0 = lo + hi;            // gate q
        upk2(ac1, lo, hi); p1 = lo + hi;            // gate q^1
        upk2(ac2, lo, hi); p2 = lo + hi;            // gate q^2
        upk2(ac3, lo, hi); p3 = lo + hi;            // gate q^3

        // ---- SEL-free xor reduce: lane q ends with gate q total ----
        const float kX = p0 + __shfl_xor_sync(0xffffffffu, p2, 2, 32);
        const float kY = p1 + __shfl_xor_sync(0xffffffffu, p3, 2, 32);
        const float tot = kX + __shfl_xor_sync(0xffffffffu, kY, 1, 32);

        // ---- input contribution + prefetch ----
        float g;
        if (DIN1) {
            g = tot + fmaf(wx, ring[slot], bias);
            const int tp = (t + 4 < SEQ) ? (t + 4) : (SEQ - 1);  // no OOB on input
            ring[slot] = xp[tp];
        } else {
            g = tot + ring[slot];
            ring[slot] = *zpref;                    // padded: no bounds check
            zpref += NG;
        }

        // ---- own-gate activation (branch-free, 1 ex2 + 1 rcp) ----
        const float a = fmaf(-sA, rcpf(ex2f(g * kA) + 1.0f), 1.0f);

        // ---- role-mapped gather (valid on q==0 lanes only) ----
        const float af = __shfl_xor_sync(0xffffffffu, a, 1, 32);
        const float ag = __shfl_xor_sync(0xffffffffu, a, 2, 32);
        const float ao = __shfl_xor_sync(0xffffffffu, a, 3, 32);
        c = fmaf(af, c, a * ag);                    // a = ai on q==0
        const float h = ao * tanh_f(c);
        hlast = h;
        if (q == 0) {
            sh[par ^ 1][20 * (u >> 4) + (u & 15)] = h;
            out_seq[((size_t)b * SEQ + t) * HID + u] = h;
        }
        __syncthreads();                            // h(t) visible
    }

    if (q == 0) {
        const size_t yoff = (size_t)NBATCH * SEQ;
        d_out[yoff + (size_t)layer * NBATCH * HID + (size_t)b * HID + u] = hlast;
        d_out[yoff + (size_t)3 * NBATCH * HID + (size_t)layer * NBATCH * HID
              + (size_t)b * HID + u] = c;
    }
}

// ---------------------------------------------------------------------------
// Final linear: y[r] = dot(g_seqA[r,:], Wlin) + blin.
// ---------------------------------------------------------------------------
__global__ void __launch_bounds__(256)
linear_kernel(const float* __restrict__ Wlin,
              const float* __restrict__ blin,
              float* __restrict__ y) {
    const int lane  = threadIdx.x & 31;
    const int warp  = (blockIdx.x * blockDim.x + threadIdx.x) >> 5;
    const int nwarp = (gridDim.x * blockDim.x) >> 5;
    const float w0 = Wlin[lane];
    const float w1 = Wlin[lane + 32];
    const float bl = blin[0];
    const int nrows = NBATCH * SEQ;
    for (int r = warp; r < nrows; r += nwarp) {
        const float* row = g_seqA + (size_t)r * HID;
        float s = row[lane] * w0 + row[lane + 32] * w1;
#pragma unroll
        for (int o = 16; o; o >>= 1) s += __shfl_down_sync(0xffffffffu, s, o);
        if (lane == 0) y[r] = s + bl;
    }
}

extern "C" void kernel_launch(void* const* d_in, const int* in_sizes, int n_in,
                              void* d_out, int out_size) {
    const float* x    = (const float*)d_in[0];
    const float* Wih0 = (const float*)d_in[1];
    const float* Whh0 = (const float*)d_in[2];
    const float* bih0 = (const float*)d_in[3];
    const float* bhh0 = (const float*)d_in[4];
    const float* Wih1 = (const float*)d_in[5];
    const float* Whh1 = (const float*)d_in[6];
    const float* bih1 = (const float*)d_in[7];
    const float* bhh1 = (const float*)d_in[8];
    const float* Wih2 = (const float*)d_in[9];
    const float* Whh2 = (const float*)d_in[10];
    const float* bih2 = (const float*)d_in[11];
    const float* bhh2 = (const float*)d_in[12];
    const float* Wlin = (const float*)d_in[13];
    const float* blin = (const float*)d_in[14];
    float* out = (float*)d_out;

    float* xzp;  cudaGetSymbolAddress((void**)&xzp, g_xz);
    float* sA;   cudaGetSymbolAddress((void**)&sA, g_seqA);
    float* sB;   cudaGetSymbolAddress((void**)&sB, g_seqB);

    // layer 0: fused input path (no xz materialization)
    lstm_rec_kernel<true><<<NBATCH, 256>>>(x, nullptr, Wih0, bih0, bhh0,
                                           Whh0, sA, out, 0);

    xz_din64_kernel<<<dim3(SEQ / 32, NBATCH), 256>>>(sA, Wih1, bih1, bhh1, xzp);
    lstm_rec_kernel<false><<<NBATCH, 256>>>(nullptr, xzp, nullptr, nullptr,
                                            nullptr, Whh1, sB, out, 1);

    xz_din64_kernel<<<dim3(SEQ / 32, NBATCH), 256>>>(sB, Wih2, bih2, bhh2, xzp);
    lstm_rec_kernel<false><<<NBATCH, 256>>>(nullptr, xzp, nullptr, nullptr,
                                            nullptr, Whh2, sA, out, 2);

    linear_kernel<<<1024, 256>>>(Wlin, blin, out);
}

// round 12
// speedup vs baseline: 1.0567x; 1.0567x over previous
#include <cuda_runtime.h>

#define HID 64
#define NBATCH 256
#define SEQ 4096
#define NG 256   // 4*HID gates

// Scratch (no cudaMalloc allowed).  g_xz has a 4*NG tail pad so the ring
// prefetch can run 4 steps past the end without bounds checks.
__device__ float g_seqA[(size_t)NBATCH * SEQ * HID];          // 256 MB
__device__ float g_seqB[(size_t)NBATCH * SEQ * HID];          // 256 MB
__device__ float g_xz[(size_t)NBATCH * SEQ * NG + 4 * NG];    // 1 GB + pad

typedef unsigned long long ull;

static __device__ __forceinline__ ull pk2(float lo, float hi) {
    ull r;
    asm("mov.b64 %0, {%1,%2};" : "=l"(r) : "f"(lo), "f"(hi));
    return r;
}
static __device__ __forceinline__ void upk2(ull v, float& lo, float& hi) {
    asm("mov.b64 {%0,%1}, %2;" : "=f"(lo), "=f"(hi) : "l"(v));
}
static __device__ __forceinline__ void ffma2(ull& d, ull a, ull b) {
    asm("fma.rn.f32x2 %0, %1, %2, %0;" : "+l"(d) : "l"(a), "l"(b));
}
static __device__ __forceinline__ float hsum8(ull a, ull b, ull c, ull d) {
    float x0, x1, y0, y1, z0, z1, w0, w1;
    upk2(a, x0, x1); upk2(b, y0, y1); upk2(c, z0, z1); upk2(d, w0, w1);
    return ((x0 + x1) + (y0 + y1)) + ((z0 + z1) + (w0 + w1));
}
static __device__ __forceinline__ float ex2f(float x) {
    float r; asm("ex2.approx.f32 %0, %1;" : "=f"(r) : "f"(x)); return r;
}
static __device__ __forceinline__ float rcpf(float x) {
    float r; asm("rcp.approx.f32 %0, %1;" : "=f"(r) : "f"(x)); return r;
}
#define L2E 1.44269504088896f
// tanh(x) = 1 - 2/(2^(2*L2E*x)+1); overflow-safe both directions.
static __device__ __forceinline__ float tanh_f(float x) {
    return fmaf(-2.0f, rcpf(ex2f(x * (2.0f * L2E)) + 1.0f), 1.0f);
}

// xz slot layout (for the 128-thread rec kernel): slot s holds gate row
//   row(s) = (p + 2k)*HID + u   with u = s>>2, p = (s>>1)&1, k = s&1
// so rec thread j = u*2+p reads its 2 gates at slots {2j, 2j+1} (one float2):
//   p=0 -> (i, g), p=1 -> (f, o)

// ---------------------------------------------------------------------------
// dummy kernel: shifts launch order so lstm_rec is the 6th launch (ncu -s 5).
// Writes to g_xz (overwritten before any consumer reads it).
// ---------------------------------------------------------------------------
__global__ void dummy_kernel() {
    g_xz[threadIdx.x] = 0.0f;
}

// ---------------------------------------------------------------------------
// xz precompute, DIN = 64 (slot layout above), layers 1-2 only.
// ---------------------------------------------------------------------------
__global__ void __launch_bounds__(256)
xz_din64_kernel(const float* __restrict__ in_seq,   // [B,SEQ,64]
                const float* __restrict__ Wih,      // [256,64]
                const float* __restrict__ bih,
                const float* __restrict__ bhh,
                float* __restrict__ xz) {
    __shared__ __align__(16) float sin_[32][HID];   // 8 KB
    const int tid = threadIdx.x;
    const int jg  = (((tid & 1) << 1) | ((tid >> 1) & 1)) * HID + (tid >> 2);
    const int b   = blockIdx.y;
    const int t0  = blockIdx.x * 32;

    const float* src = in_seq + ((size_t)b * SEQ + t0) * HID;
#pragma unroll
    for (int k = 0; k < 8; ++k)
        ((float*)sin_)[tid + k * 256] = src[tid + k * 256];

    ull wi[32];
#pragma unroll
    for (int p = 0; p < 32; ++p)
        wi[p] = pk2(Wih[jg * HID + 2 * p], Wih[jg * HID + 2 * p + 1]);
    const float bias = bih[jg] + bhh[jg];
    __syncthreads();

    float* o = xz + ((size_t)b * SEQ + t0) * NG + tid;
#pragma unroll 4
    for (int tt = 0; tt < 32; ++tt) {
        const ulonglong2* v = (const ulonglong2*)&sin_[tt][0];
        ull a0 = pk2(bias, 0.0f), a1 = 0ULL;
#pragma unroll
        for (int p = 0; p < 16; ++p) {
            ulonglong2 q = v[p];
            ffma2(a0, wi[2 * p], q.x);
            ffma2(a1, wi[2 * p + 1], q.y);
        }
        float l0, l1, h0, h1;
        upk2(a0, l0, h0); upk2(a1, l1, h1);
        o[(size_t)tt * NG] = (l0 + h0) + (l1 + h1);
    }
}

// ---------------------------------------------------------------------------
// Recurrent kernel v6.  1 batch/CTA, 256 CTAs x 128 threads, 2 CTAs/SM.
// Thread j = (u = j>>1, p = j&1) computes FULL 64-dots of 2 gates:
//   gate A = type p   (i or f, always sigmoid)
//   gate B = type 2+p (g or o; tanh iff p==0)
// No reduce-scatter shuffles (full dots).  Pair exchange: 2x shfl_xor(1).
// p==0 lanes own unit u's (c,h).  4-warp barrier, h double-buffered in smem.
// ---------------------------------------------------------------------------
template <bool DIN1>
__global__ void __launch_bounds__(128, 2)
lstm_rec_kernel(const float* __restrict__ x,        // DIN1: [B,SEQ]
                const float* __restrict__ xz,       // !DIN1: [B,SEQ,256] slotted
                const float* __restrict__ Wih,      // DIN1: [256,1]
                const float* __restrict__ bih,
                const float* __restrict__ bhh,
                const float* __restrict__ Whh,      // [256,64]
                float* __restrict__ out_seq,        // [B,SEQ,64]
                float* __restrict__ d_out,
                int layer) {
    __shared__ __align__(16) float sh[2][HID];      // double-buffered h

    const int tid = threadIdx.x;                    // 0..127
    const int b   = blockIdx.x;
    const int u   = tid >> 1;
    const int p   = tid & 1;
    const int rA  = p * HID + u;                    // i or f row
    const int rB  = (2 + p) * HID + u;              // g or o row

    ull wA[32], wB[32];
#pragma unroll
    for (int m = 0; m < 32; ++m) {
        wA[m] = pk2(Whh[rA * HID + 2 * m], Whh[rA * HID + 2 * m + 1]);
        wB[m] = pk2(Whh[rB * HID + 2 * m], Whh[rB * HID + 2 * m + 1]);
    }

    // input-contribution state (2 gates per thread)
    float wxA = 0.0f, wxB = 0.0f, biasA = 0.0f, biasB = 0.0f;
    const float* xp = nullptr;
    const float2* zpref = nullptr;
    float2 ring[4];
    if (DIN1) {
        wxA = Wih[rA]; wxB = Wih[rB];
        biasA = bih[rA] + bhh[rA];
        biasB = bih[rB] + bhh[rB];
        xp = x + (size_t)b * SEQ;
        float xv0 = xp[0], xv1 = xp[1], xv2 = xp[2], xv3 = xp[3];
        ring[0] = make_float2(xv0, xv0);   // store raw x in .x (reuse .y unused)
        ring[1] = make_float2(xv1, xv1);
        ring[2] = make_float2(xv2, xv2);
        ring[3] = make_float2(xv3, xv3);
    } else {
        const float2* z = (const float2*)(xz + (size_t)b * SEQ * NG) + tid;
#pragma unroll
        for (int d = 0; d < 4; ++d) ring[d] = z[(size_t)d * (NG / 2)];
        zpref = z + (size_t)4 * (NG / 2);
    }

    // gate B activation select: tanh iff p==0
    const float sB = (p == 0) ? 2.0f : 1.0f;
    const float kB = sB * L2E;

    float c = 0.0f, hlast = 0.0f;
    if (tid < 128) sh[tid >> 6][tid & 63] = 0.0f;
    __syncthreads();

#pragma unroll 4
    for (int t = 0; t < SEQ; ++t) {
        const int par  = t & 1;                     // static under unroll
        const int slot = t & 3;

        // ---- full 64-dots for 2 gates (broadcast LDS, 8-deep chains) ----
        const ulonglong2* v = (const ulonglong2*)&sh[par][0];
        ull aA[4] = {0ULL, 0ULL, 0ULL, 0ULL};
        ull aB[4] = {0ULL, 0ULL, 0ULL, 0ULL};
#pragma unroll
        for (int i = 0; i < 4; ++i) {
#pragma unroll
            for (int m = 0; m < 4; ++m) {
                const ulonglong2 q = v[i * 4 + m];
                ffma2(aA[m], wA[(i * 4 + m) * 2], q.x);
                ffma2(aA[m], wA[(i * 4 + m) * 2 + 1], q.y);
                ffma2(aB[m], wB[(i * 4 + m) * 2], q.x);
                ffma2(aB[m], wB[(i * 4 + m) * 2 + 1], q.y);
            }
        }
        float gA = hsum8(aA[0], aA[1], aA[2], aA[3]);
        float gB = hsum8(aB[0], aB[1], aB[2], aB[3]);

        // ---- input contribution + prefetch ----
        if (DIN1) {
            const float xv = ring[slot].x;
            gA += fmaf(wxA, xv, biasA);
            gB += fmaf(wxB, xv, biasB);
            const int tp = (t + 4 < SEQ) ? (t + 4) : (SEQ - 1);  // no OOB on input
            const float xn = xp[tp];
            ring[slot] = make_float2(xn, xn);
        } else {
            gA += ring[slot].x;
            gB += ring[slot].y;
            ring[slot] = *zpref;                    // padded: no bounds check
            zpref += NG / 2;
        }

        // ---- activations: A = sigmoid, B = tanh (p0) / sigmoid (p1) ----
        const float actA = fmaf(-1.0f, rcpf(ex2f(gA * L2E) + 1.0f), 1.0f);
        const float actB = fmaf(-sB, rcpf(ex2f(gB * kB) + 1.0f), 1.0f);

        // ---- pair exchange: p0 gets (f,o) from p1 ----
        const float oA = __shfl_xor_sync(0xffffffffu, actA, 1, 32);  // p0: f
        const float oB = __shfl_xor_sync(0xffffffffu, actB, 1, 32);  // p0: o
        c = fmaf(oA, c, actA * actB);               // p0: f*c + i*g
        const float h = oB * tanh_f(c);             // p0: o*tanh(c)
        hlast = h;
        if (p == 0) {
            sh[par ^ 1][u] = h;
            out_seq[((size_t)b * SEQ + t) * HID + u] = h;
        }
        __syncthreads();                            // h(t) visible
    }

    if (p == 0) {
        const size_t yoff = (size_t)NBATCH * SEQ;
        d_out[yoff + (size_t)layer * NBATCH * HID + (size_t)b * HID + u] = hlast;
        d_out[yoff + (size_t)3 * NBATCH * HID + (size_t)layer * NBATCH * HID
              + (size_t)b * HID + u] = c;
    }
}

// ---------------------------------------------------------------------------
// Final linear: y[r] = dot(g_seqA[r,:], Wlin) + blin.
// ---------------------------------------------------------------------------
__global__ void __launch_bounds__(256)
linear_kernel(const float* __restrict__ Wlin,
              const float* __restrict__ blin,
              float* __restrict__ y) {
    const int lane  = threadIdx.x & 31;
    const int warp  = (blockIdx.x * blockDim.x + threadIdx.x) >> 5;
    const int nwarp = (gridDim.x * blockDim.x) >> 5;
    const float w0 = Wlin[lane];
    const float w1 = Wlin[lane + 32];
    const float bl = blin[0];
    const int nrows = NBATCH * SEQ;
    for (int r = warp; r < nrows; r += nwarp) {
        const float* row = g_seqA + (size_t)r * HID;
        float s = row[lane] * w0 + row[lane + 32] * w1;
#pragma unroll
        for (int o = 16; o; o >>= 1) s += __shfl_down_sync(0xffffffffu, s, o);
        if (lane == 0) y[r] = s + bl;
    }
}

extern "C" void kernel_launch(void* const* d_in, const int* in_sizes, int n_in,
                              void* d_out, int out_size) {
    const float* x    = (const float*)d_in[0];
    const float* Wih0 = (const float*)d_in[1];
    const float* Whh0 = (const float*)d_in[2];
    const float* bih0 = (const float*)d_in[3];
    const float* bhh0 = (const float*)d_in[4];
    const float* Wih1 = (const float*)d_in[5];
    const float* Whh1 = (const float*)d_in[6];
    const float* bih1 = (const float*)d_in[7];
    const float* bhh1 = (const float*)d_in[8];
    const float* Wih2 = (const float*)d_in[9];
    const float* Whh2 = (const float*)d_in[10];
    const float* bih2 = (const float*)d_in[11];
    const float* bhh2 = (const float*)d_in[12];
    const float* Wlin = (const float*)d_in[13];
    const float* blin = (const float*)d_in[14];
    float* out = (float*)d_out;

    float* xzp;  cudaGetSymbolAddress((void**)&xzp, g_xz);
    float* sA;   cudaGetSymbolAddress((void**)&sA, g_seqA);
    float* sB;   cudaGetSymbolAddress((void**)&sB, g_seqB);

    dummy_kernel<<<1, 256>>>();   // launch #1: aligns lstm_rec to ncu -s 5

    // layer 0: fused input path (no xz materialization)
    lstm_rec_kernel<true><<<NBATCH, 128>>>(x, nullptr, Wih0, bih0, bhh0,
                                           Whh0, sA, out, 0);

    xz_din64_kernel<<<dim3(SEQ / 32, NBATCH), 256>>>(sA, Wih1, bih1, bhh1, xzp);
    lstm_rec_kernel<false><<<NBATCH, 128>>>(nullptr, xzp, nullptr, nullptr,
                                            nullptr, Whh1, sB, out, 1);

    xz_din64_kernel<<<dim3(SEQ / 32, NBATCH), 256>>>(sB, Wih2, bih2, bhh2, xzp);
    lstm_rec_kernel<false><<<NBATCH, 128>>>(nullptr, xzp, nullptr, nullptr,
                                            nullptr, Whh2, sA, out, 2);   // launch #6

    linear_kernel<<<1024, 256>>>(Wlin, blin, out);
}